// round 5
// baseline (speedup 1.0000x reference)
#include <cuda_runtime.h>
#include <cuda_bf16.h>
#include <cstdint>
#include <math.h>

// ---------------------------------------------------------------------------
// Problem: x[4,2048,1024] f32; W_qkv[1024,3072]; W_o[1024,1024]; out[4,2048,1024]
//   1) split x -> A' bf16 [8192, 3072]  (hi | lo | hi along K)
//   2) split/transpose W_qkv -> B' bf16 [3072, 3072] (hi ; hi ; lo)
//   3) HMMA bf16 GEMM (64x64 warp tiles, 4-stage pipe) -> g_qkv f32
//   4) tf32 mma flash-style anti-causal attention -> g_attn
//   5) split g_attn -> A' ; split/transpose W_o -> B'
//   6) HMMA bf16 GEMM -> out
// ---------------------------------------------------------------------------
#define BB 4
#define NN 2048
#define DD 1024
#define HH 16
#define EE 64
#define MTOT (BB * NN)   // 8192
#define KP   3072
#define SA   40          // gemm smem row stride in bf16 (32 data + 8 pad)
#define NSTAGE 96        // KP / 32
#define PIPE 4

__device__ float         g_qkv[MTOT * 3 * DD];
__device__ float         g_attn[MTOT * DD];
__device__ __nv_bfloat16 g_A[MTOT * KP];
__device__ __nv_bfloat16 g_B[3 * DD * KP];

// ===========================================================================
__device__ __forceinline__ uint32_t smem_u32(const void* p) {
    uint32_t a;
    asm("{ .reg .u64 t; cvta.to.shared.u64 t, %1; cvt.u32.u64 %0, t; }"
        : "=r"(a) : "l"(p));
    return a;
}
__device__ __forceinline__ void cp_async16(uint32_t dst, const void* src) {
    asm volatile("cp.async.cg.shared.global [%0], [%1], 16;"
                 :: "r"(dst), "l"(src) : "memory");
}
__device__ __forceinline__ void ldsm_x4(uint32_t* r, uint32_t addr) {
    asm volatile("ldmatrix.sync.aligned.m8n8.x4.shared.b16 {%0,%1,%2,%3}, [%4];"
                 : "=r"(r[0]), "=r"(r[1]), "=r"(r[2]), "=r"(r[3]) : "r"(addr));
}
__device__ __forceinline__ void mma_bf16(float* d, const uint32_t* a, const uint32_t* b) {
    asm volatile(
        "mma.sync.aligned.m16n8k16.row.col.f32.bf16.bf16.f32 "
        "{%0,%1,%2,%3}, {%4,%5,%6,%7}, {%8,%9}, {%0,%1,%2,%3};"
        : "+f"(d[0]), "+f"(d[1]), "+f"(d[2]), "+f"(d[3])
        : "r"(a[0]), "r"(a[1]), "r"(a[2]), "r"(a[3]), "r"(b[0]), "r"(b[1]));
}
__device__ __forceinline__ float tf32r(float x) {
    asm("cvt.rna.tf32.f32 %0, %0;" : "+f"(x));
    return x;
}
__device__ __forceinline__ void mma_tf32(float* d, const float* a, float b0f, float b1f) {
    uint32_t a0 = __float_as_uint(a[0]), a1 = __float_as_uint(a[1]);
    uint32_t a2 = __float_as_uint(a[2]), a3 = __float_as_uint(a[3]);
    uint32_t b0 = __float_as_uint(b0f), b1 = __float_as_uint(b1f);
    asm volatile(
        "mma.sync.aligned.m16n8k8.row.col.f32.tf32.tf32.f32 "
        "{%0,%1,%2,%3}, {%4,%5,%6,%7}, {%8,%9}, {%0,%1,%2,%3};"
        : "+f"(d[0]), "+f"(d[1]), "+f"(d[2]), "+f"(d[3])
        : "r"(a0), "r"(a1), "r"(a2), "r"(a3), "r"(b0), "r"(b1));
}

// ===========================================================================
// HMMA GEMM: C[M,Nn] f32 = A[M,KP] bf16 @ B[Nn,KP]^T bf16
// CTA 128x128, 4 warps of 64x64, BK=32, 4-stage cp.async ring.
// ===========================================================================
#define BUFB (128 * SA * 2)                    // 10240 B per matrix per stage
#define SMEM_GEMM (PIPE * 2 * BUFB)            // 81920

__global__ __launch_bounds__(128, 2)
void gemm_hmma(const __nv_bfloat16* __restrict__ A,
               const __nv_bfloat16* __restrict__ B,
               float* __restrict__ C, int M, int Nn) {
    extern __shared__ __nv_bfloat16 smbf[];
    const int tid  = threadIdx.x;
    const int wid  = tid >> 5;
    const int lane = tid & 31;
    const int m0 = blockIdx.y * 128;
    const int n0 = blockIdx.x * 128;
    const int wm = (wid >> 1) * 64;   // warp row offset
    const int wn = (wid & 1) * 64;    // warp col offset

    const uint32_t sbase = smem_u32(smbf);
    const uint32_t aoff0 = sbase;
    const uint32_t boff0 = sbase + PIPE * BUFB;

    const __nv_bfloat16* Ag = A + (size_t)m0 * KP;
    const __nv_bfloat16* Bg = B + (size_t)n0 * KP;

    // each thread loads row tid of A and B, 4 x 16B chunks (full BK=32)
    auto load_stage = [&](int s) {
        const int buf = s & (PIPE - 1);
        const uint32_t ab = aoff0 + buf * BUFB;
        const uint32_t bb = boff0 + buf * BUFB;
        const int k0 = s * 32;
        const __nv_bfloat16* arow = Ag + (size_t)tid * KP + k0;
        const __nv_bfloat16* brow = Bg + (size_t)tid * KP + k0;
        const uint32_t doff = (uint32_t)(tid * SA) * 2;
#pragma unroll
        for (int c = 0; c < 4; c++) {
            cp_async16(ab + doff + c * 16, arow + c * 8);
            cp_async16(bb + doff + c * 16, brow + c * 8);
        }
        asm volatile("cp.async.commit_group;" ::: "memory");
    };

    float acc[4][8][4];
#pragma unroll
    for (int i = 0; i < 4; i++)
#pragma unroll
        for (int j = 0; j < 8; j++)
#pragma unroll
            for (int k = 0; k < 4; k++) acc[i][j][k] = 0.0f;

    const int arow  = wm + (lane & 15);
    const int akoff = (lane >> 4) * 8;
    const int brow  = wn + (lane >> 4) * 8 + (lane & 7);
    const int bkoff = ((lane >> 3) & 1) * 8;

    load_stage(0);
    load_stage(1);
    load_stage(2);

    for (int s = 0; s < NSTAGE; s++) {
        const int pend = NSTAGE - 1 - s;
        if (pend >= 2)      asm volatile("cp.async.wait_group 2;" ::: "memory");
        else if (pend == 1) asm volatile("cp.async.wait_group 1;" ::: "memory");
        else                asm volatile("cp.async.wait_group 0;" ::: "memory");
        __syncthreads();
        if (s + 3 < NSTAGE) load_stage(s + 3);

        const int buf = s & (PIPE - 1);
        const uint32_t ab = aoff0 + buf * BUFB;
        const uint32_t bb = boff0 + buf * BUFB;

#pragma unroll
        for (int ksub = 0; ksub < 2; ksub++) {
            uint32_t af[4][4], bf[4][4];
#pragma unroll
            for (int mt = 0; mt < 4; mt++)
                ldsm_x4(af[mt], ab + (uint32_t)((arow + mt * 16) * SA + ksub * 16 + akoff) * 2);
#pragma unroll
            for (int p = 0; p < 4; p++)
                ldsm_x4(bf[p], bb + (uint32_t)((brow + p * 16) * SA + ksub * 16 + bkoff) * 2);
#pragma unroll
            for (int mt = 0; mt < 4; mt++) {
#pragma unroll
                for (int nt = 0; nt < 8; nt++)
                    mma_bf16(acc[mt][nt], af[mt], &bf[nt >> 1][(nt & 1) * 2]);
            }
        }
    }

    // epilogue: direct float2 stores
    const int grp = lane >> 2;
    const int tig = lane & 3;
#pragma unroll
    for (int mt = 0; mt < 4; mt++) {
#pragma unroll
        for (int nt = 0; nt < 8; nt++) {
            const int row = m0 + wm + mt * 16 + grp;
            const int col = n0 + wn + nt * 8 + tig * 2;
            float2 v0 = make_float2(acc[mt][nt][0], acc[mt][nt][1]);
            float2 v1 = make_float2(acc[mt][nt][2], acc[mt][nt][3]);
            *(float2*)&C[(size_t)row * Nn + col]       = v0;
            *(float2*)&C[(size_t)(row + 8) * Nn + col] = v1;
        }
    }
}

// ===========================================================================
// Conversion kernels (unchanged)
// ===========================================================================
__global__ __launch_bounds__(256)
void split_rows(const float* __restrict__ in, __nv_bfloat16* __restrict__ out, int M) {
    int idx = blockIdx.x * 256 + threadIdx.x;
    if (idx >= M * DD) return;
    int m = idx >> 10, k = idx & 1023;
    float x = in[idx];
    __nv_bfloat16 hi = __float2bfloat16(x);
    __nv_bfloat16 lo = __float2bfloat16(x - __bfloat162float(hi));
    __nv_bfloat16* o = out + (size_t)m * KP;
    o[k] = hi; o[DD + k] = lo; o[2 * DD + k] = hi;
}

__global__ __launch_bounds__(256)
void split_transpose(const float* __restrict__ W, __nv_bfloat16* __restrict__ out, int Nw) {
    __shared__ float t[32][33];
    int n0 = blockIdx.x * 32, k0 = blockIdx.y * 32;
    int tx = threadIdx.x, ty = threadIdx.y;
#pragma unroll
    for (int i = ty; i < 32; i += 8)
        t[i][tx] = W[(size_t)(k0 + i) * Nw + n0 + tx];
    __syncthreads();
#pragma unroll
    for (int i = ty; i < 32; i += 8) {
        int n = n0 + i, k = k0 + tx;
        float x = t[tx][i];
        __nv_bfloat16 hi = __float2bfloat16(x);
        __nv_bfloat16 lo = __float2bfloat16(x - __bfloat162float(hi));
        __nv_bfloat16* o = out + (size_t)n * KP;
        o[k] = hi; o[DD + k] = hi; o[2 * DD + k] = lo;
    }
}

// ===========================================================================
// Attention with tf32 mma — unchanged from R4 (passing, 386us)
// ===========================================================================
#define AT_I 128
#define AT_J 64
#define STRD 68
#define SMEM_ATTN ((AT_I + AT_J + AT_J) * STRD * (int)sizeof(float))

__global__ __launch_bounds__(256, 2)
void attn_tc(const float* __restrict__ qkv, float* __restrict__ outp) {
    extern __shared__ float sm[];
    float* Ksm = sm;
    float* Qsm = sm + AT_I * STRD;
    float* Vsm = sm + (AT_I + AT_J) * STRD;

    const int it = blockIdx.x;
    const int bh = blockIdx.y;
    const int b = bh >> 4, h = bh & 15;
    const int i0 = it * AT_I;

    const int tid  = threadIdx.x;
    const int wid  = tid >> 5;
    const int lane = tid & 31;
    const int g = lane >> 2;
    const int t = lane & 3;
    const int wm = wid * 16;

    const size_t RS = 3 * DD;
    const float* Qg = qkv + h * EE;
    const float* Kg = qkv + DD + h * EE;
    const float* Vg = qkv + 2 * DD + h * EE;

#pragma unroll
    for (int q = 0; q < 8; q++) {
        int idx = q * 256 + tid;
        int r = idx >> 4, ec = (idx & 15) << 2;
        float4 v = *(const float4*)(Kg + (size_t)(b * NN + i0 + r) * RS + ec);
        float* d = Ksm + r * STRD + ec;
        d[0] = tf32r(v.x); d[1] = tf32r(v.y); d[2] = tf32r(v.z); d[3] = tf32r(v.w);
    }

    float m0 = -1e30f, m1 = -1e30f, l0 = 0.0f, l1 = 0.0f;
    float O[8][4];
#pragma unroll
    for (int nt = 0; nt < 8; nt++)
#pragma unroll
        for (int k = 0; k < 4; k++) O[nt][k] = 0.0f;

    const int r0g = i0 + wm + g;
    const int r1g = r0g + 8;

    const int jt0 = it * 2;
    const int nJT = NN / AT_J;

    for (int jt = jt0; jt < nJT; jt++) {
        const int j0 = jt * AT_J;
        __syncthreads();

#pragma unroll
        for (int q = 0; q < 4; q++) {
            int idx = q * 256 + tid;
            int r = idx >> 4, ec = (idx & 15) << 2;
            float4 v = *(const float4*)(Qg + (size_t)(b * NN + j0 + r) * RS + ec);
            float* d = Qsm + r * STRD + ec;
            d[0] = tf32r(v.x); d[1] = tf32r(v.y); d[2] = tf32r(v.z); d[3] = tf32r(v.w);
        }
#pragma unroll
        for (int q = 0; q < 4; q++) {
            int ec = (wid * 2 + (q >> 1)) << 2;
            int j  = ((q & 1) << 5) + lane;
            float4 v = *(const float4*)(Vg + (size_t)(b * NN + j0 + j) * RS + ec);
            Vsm[(ec + 0) * STRD + j] = tf32r(v.x);
            Vsm[(ec + 1) * STRD + j] = tf32r(v.y);
            Vsm[(ec + 2) * STRD + j] = tf32r(v.z);
            Vsm[(ec + 3) * STRD + j] = tf32r(v.w);
        }
        __syncthreads();

        float C[8][4];
#pragma unroll
        for (int nt = 0; nt < 8; nt++)
#pragma unroll
            for (int k = 0; k < 4; k++) C[nt][k] = 0.0f;

#pragma unroll
        for (int kt = 0; kt < 8; kt++) {
            float a[4];
            a[0] = Ksm[(wm + g)     * STRD + kt * 8 + t];
            a[1] = Ksm[(wm + g + 8) * STRD + kt * 8 + t];
            a[2] = Ksm[(wm + g)     * STRD + kt * 8 + t + 4];
            a[3] = Ksm[(wm + g + 8) * STRD + kt * 8 + t + 4];
#pragma unroll
            for (int nt = 0; nt < 8; nt++) {
                float b0 = Qsm[(nt * 8 + g) * STRD + kt * 8 + t];
                float b1 = Qsm[(nt * 8 + g) * STRD + kt * 8 + t + 4];
                mma_tf32(C[nt], a, b0, b1);
            }
        }

        const bool needmask = (j0 < i0 + AT_I);
        float rmax0 = -1e30f, rmax1 = -1e30f;
#pragma unroll
        for (int nt = 0; nt < 8; nt++) {
            C[nt][0] *= 0.125f; C[nt][1] *= 0.125f;
            C[nt][2] *= 0.125f; C[nt][3] *= 0.125f;
            if (needmask) {
                int c0 = j0 + nt * 8 + 2 * t;
                int c1 = c0 + 1;
                if (c0 < r0g) C[nt][0] = -1e30f;
                if (c1 < r0g) C[nt][1] = -1e30f;
                if (c0 < r1g) C[nt][2] = -1e30f;
                if (c1 < r1g) C[nt][3] = -1e30f;
            }
            rmax0 = fmaxf(rmax0, fmaxf(C[nt][0], C[nt][1]));
            rmax1 = fmaxf(rmax1, fmaxf(C[nt][2], C[nt][3]));
        }
        rmax0 = fmaxf(rmax0, __shfl_xor_sync(0xffffffffu, rmax0, 1));
        rmax0 = fmaxf(rmax0, __shfl_xor_sync(0xffffffffu, rmax0, 2));
        rmax1 = fmaxf(rmax1, __shfl_xor_sync(0xffffffffu, rmax1, 1));
        rmax1 = fmaxf(rmax1, __shfl_xor_sync(0xffffffffu, rmax1, 2));

        float mn0 = fmaxf(m0, rmax0), mn1 = fmaxf(m1, rmax1);
        float sc0 = __expf(m0 - mn0), sc1 = __expf(m1 - mn1);
        m0 = mn0; m1 = mn1;

        float rs0 = 0.0f, rs1 = 0.0f;
#pragma unroll
        for (int nt = 0; nt < 8; nt++) {
            C[nt][0] = __expf(C[nt][0] - mn0);
            C[nt][1] = __expf(C[nt][1] - mn0);
            C[nt][2] = __expf(C[nt][2] - mn1);
            C[nt][3] = __expf(C[nt][3] - mn1);
            rs0 += C[nt][0] + C[nt][1];
            rs1 += C[nt][2] + C[nt][3];
        }
        rs0 += __shfl_xor_sync(0xffffffffu, rs0, 1);
        rs0 += __shfl_xor_sync(0xffffffffu, rs0, 2);
        rs1 += __shfl_xor_sync(0xffffffffu, rs1, 1);
        rs1 += __shfl_xor_sync(0xffffffffu, rs1, 2);
        l0 = l0 * sc0 + rs0;
        l1 = l1 * sc1 + rs1;
#pragma unroll
        for (int nt = 0; nt < 8; nt++) {
            O[nt][0] *= sc0; O[nt][1] *= sc0;
            O[nt][2] *= sc1; O[nt][3] *= sc1;
        }

        const uint32_t srcA = (lane & 28) | (t >> 1);
        const uint32_t srcB = srcA + 2;
#pragma unroll
        for (int kt = 0; kt < 8; kt++) {
            float p0a = __shfl_sync(0xffffffffu, C[kt][0], srcA);
            float p1a = __shfl_sync(0xffffffffu, C[kt][1], srcA);
            float p2a = __shfl_sync(0xffffffffu, C[kt][2], srcA);
            float p3a = __shfl_sync(0xffffffffu, C[kt][3], srcA);
            float p0b = __shfl_sync(0xffffffffu, C[kt][0], srcB);
            float p1b = __shfl_sync(0xffffffffu, C[kt][1], srcB);
            float p2b = __shfl_sync(0xffffffffu, C[kt][2], srcB);
            float p3b = __shfl_sync(0xffffffffu, C[kt][3], srcB);
            float a[4];
            a[0] = tf32r((t & 1) ? p1a : p0a);
            a[1] = tf32r((t & 1) ? p3a : p2a);
            a[2] = tf32r((t & 1) ? p1b : p0b);
            a[3] = tf32r((t & 1) ? p3b : p2b);
#pragma unroll
            for (int nt = 0; nt < 8; nt++) {
                float b0 = Vsm[(nt * 8 + g) * STRD + kt * 8 + t];
                float b1 = Vsm[(nt * 8 + g) * STRD + kt * 8 + t + 4];
                mma_tf32(O[nt], a, b0, b1);
            }
        }
    }

    float inv0 = 1.0f / l0, inv1 = 1.0f / l1;
    float* out0 = outp + (size_t)(b * NN + r0g) * DD + h * EE;
    float* out1 = outp + (size_t)(b * NN + r1g) * DD + h * EE;
#pragma unroll
    for (int nt = 0; nt < 8; nt++) {
        int col = nt * 8 + 2 * t;
        *(float2*)(out0 + col) = make_float2(O[nt][0] * inv0, O[nt][1] * inv0);
        *(float2*)(out1 + col) = make_float2(O[nt][2] * inv1, O[nt][3] * inv1);
    }
}

// ===========================================================================
extern "C" void kernel_launch(void* const* d_in, const int* in_sizes, int n_in,
                              void* d_out, int out_size) {
    const float* x    = (const float*)d_in[0];
    const float* Wqkv = (const float*)d_in[1];
    const float* Wo   = (const float*)d_in[2];
    float* out = (float*)d_out;

    float* qkv = nullptr;  float* attn = nullptr;
    __nv_bfloat16* Abuf = nullptr;  __nv_bfloat16* Bbuf = nullptr;
    cudaGetSymbolAddress((void**)&qkv,  g_qkv);
    cudaGetSymbolAddress((void**)&attn, g_attn);
    cudaGetSymbolAddress((void**)&Abuf, g_A);
    cudaGetSymbolAddress((void**)&Bbuf, g_B);

    cudaFuncSetAttribute(gemm_hmma, cudaFuncAttributeMaxDynamicSharedMemorySize, SMEM_GEMM);
    cudaFuncSetAttribute(attn_tc, cudaFuncAttributeMaxDynamicSharedMemorySize, SMEM_ATTN);

    // 1) x -> A' split
    split_rows<<<(MTOT * DD + 255) / 256, 256>>>(x, Abuf, MTOT);
    // 2) W_qkv -> B' split-transpose
    split_transpose<<<dim3(3 * DD / 32, DD / 32), dim3(32, 8)>>>(Wqkv, Bbuf, 3 * DD);
    // 3) QKV GEMM
    gemm_hmma<<<dim3(3 * DD / 128, MTOT / 128), 128, SMEM_GEMM>>>(Abuf, Bbuf, qkv, MTOT, 3 * DD);
    // 4) attention (tf32 tensor cores)
    attn_tc<<<dim3(NN / AT_I, BB * HH), 256, SMEM_ATTN>>>(qkv, attn);
    // 5) attn out -> A' ; W_o -> B'
    split_rows<<<(MTOT * DD + 255) / 256, 256>>>(attn, Abuf, MTOT);
    split_transpose<<<dim3(DD / 32, DD / 32), dim3(32, 8)>>>(Wo, Bbuf, DD);
    // 6) O-proj GEMM
    gemm_hmma<<<dim3(DD / 128, MTOT / 128), 128, SMEM_GEMM>>>(Abuf, Bbuf, out, MTOT, DD);
}

// round 6
// speedup vs baseline: 1.1067x; 1.1067x over previous
#include <cuda_runtime.h>
#include <cuda_bf16.h>
#include <cstdint>
#include <math.h>

// ---------------------------------------------------------------------------
// Problem: x[4,2048,1024] f32; W_qkv[1024,3072]; W_o[1024,1024]; out[4,2048,1024]
//   1) split x -> A' bf16 [8192, 3072]  (hi | lo | hi along K)
//   2) split/transpose W_qkv -> B' bf16 [3072, 3072] (hi ; hi ; lo)
//   3) HMMA bf16 GEMM (R3 shape: 8 warps 64x32, now 4-stage pipe) -> g_qkv
//   4) tf32 mma flash-style anti-causal attention -> g_attn
//   5) split g_attn -> A' ; split/transpose W_o -> B'
//   6) HMMA bf16 GEMM -> out
// ---------------------------------------------------------------------------
#define BB 4
#define NN 2048
#define DD 1024
#define HH 16
#define EE 64
#define MTOT (BB * NN)   // 8192
#define KP   3072
#define SA   40          // gemm smem row stride in bf16 (32 data + 8 pad)
#define NSTAGE 96        // KP / 32
#define PIPE 4

__device__ float         g_qkv[MTOT * 3 * DD];
__device__ float         g_attn[MTOT * DD];
__device__ __nv_bfloat16 g_A[MTOT * KP];
__device__ __nv_bfloat16 g_B[3 * DD * KP];

// ===========================================================================
__device__ __forceinline__ uint32_t smem_u32(const void* p) {
    uint32_t a;
    asm("{ .reg .u64 t; cvta.to.shared.u64 t, %1; cvt.u32.u64 %0, t; }"
        : "=r"(a) : "l"(p));
    return a;
}
__device__ __forceinline__ void cp_async16(uint32_t dst, const void* src) {
    asm volatile("cp.async.cg.shared.global [%0], [%1], 16;"
                 :: "r"(dst), "l"(src) : "memory");
}
__device__ __forceinline__ void ldsm_x4(uint32_t* r, uint32_t addr) {
    asm volatile("ldmatrix.sync.aligned.m8n8.x4.shared.b16 {%0,%1,%2,%3}, [%4];"
                 : "=r"(r[0]), "=r"(r[1]), "=r"(r[2]), "=r"(r[3]) : "r"(addr));
}
__device__ __forceinline__ void mma_bf16(float* d, const uint32_t* a, const uint32_t* b) {
    asm volatile(
        "mma.sync.aligned.m16n8k16.row.col.f32.bf16.bf16.f32 "
        "{%0,%1,%2,%3}, {%4,%5,%6,%7}, {%8,%9}, {%0,%1,%2,%3};"
        : "+f"(d[0]), "+f"(d[1]), "+f"(d[2]), "+f"(d[3])
        : "r"(a[0]), "r"(a[1]), "r"(a[2]), "r"(a[3]), "r"(b[0]), "r"(b[1]));
}
__device__ __forceinline__ float tf32r(float x) {
    asm("cvt.rna.tf32.f32 %0, %0;" : "+f"(x));
    return x;
}
__device__ __forceinline__ void mma_tf32(float* d, const float* a, float b0f, float b1f) {
    uint32_t a0 = __float_as_uint(a[0]), a1 = __float_as_uint(a[1]);
    uint32_t a2 = __float_as_uint(a[2]), a3 = __float_as_uint(a[3]);
    uint32_t b0 = __float_as_uint(b0f), b1 = __float_as_uint(b1f);
    asm volatile(
        "mma.sync.aligned.m16n8k8.row.col.f32.tf32.tf32.f32 "
        "{%0,%1,%2,%3}, {%4,%5,%6,%7}, {%8,%9}, {%0,%1,%2,%3};"
        : "+f"(d[0]), "+f"(d[1]), "+f"(d[2]), "+f"(d[3])
        : "r"(a0), "r"(a1), "r"(a2), "r"(a3), "r"(b0), "r"(b1));
}

// ===========================================================================
// HMMA GEMM: C[M,Nn] f32 = A[M,KP] bf16 @ B[Nn,KP]^T bf16
// R3 shape: CTA 128x128, 8 warps of 64x32, BK=32; 4-stage cp.async ring.
// ===========================================================================
#define BUFB (128 * SA * 2)                    // 10240 B per matrix per stage
#define SMEM_GEMM (PIPE * 2 * BUFB)            // 81920

__global__ __launch_bounds__(256, 2)
void gemm_hmma(const __nv_bfloat16* __restrict__ A,
               const __nv_bfloat16* __restrict__ B,
               float* __restrict__ C, int M, int Nn) {
    extern __shared__ __nv_bfloat16 smbf[];
    const int tid  = threadIdx.x;
    const int wid  = tid >> 5;
    const int lane = tid & 31;
    const int m0 = blockIdx.y * 128;
    const int n0 = blockIdx.x * 128;
    const int wm = (wid >> 2) * 64;   // warp row offset
    const int wn = (wid & 3) * 32;    // warp col offset

    const uint32_t sbase = smem_u32(smbf);
    const uint32_t aoff0 = sbase;
    const uint32_t boff0 = sbase + PIPE * BUFB;

    const __nv_bfloat16* Ag = A + (size_t)m0 * KP;
    const __nv_bfloat16* Bg = B + (size_t)n0 * KP;

    // global->smem mapping: thread -> row tid/2, two 16B chunks
    const int lr  = tid >> 1;
    const int lkc = (tid & 1) * 2;

    auto load_stage = [&](int s) {
        const int buf = s & (PIPE - 1);
        const uint32_t ab = aoff0 + buf * BUFB;
        const uint32_t bb = boff0 + buf * BUFB;
        const int k0 = s * 32;
#pragma unroll
        for (int j = 0; j < 2; j++) {
            const int kc = lkc + j;
            const uint32_t doff = (uint32_t)(lr * SA + kc * 8) * 2;
            cp_async16(ab + doff, Ag + (size_t)lr * KP + k0 + kc * 8);
            cp_async16(bb + doff, Bg + (size_t)lr * KP + k0 + kc * 8);
        }
        asm volatile("cp.async.commit_group;" ::: "memory");
    };

    float acc[4][4][4];
#pragma unroll
    for (int i = 0; i < 4; i++)
#pragma unroll
        for (int j = 0; j < 4; j++)
#pragma unroll
            for (int k = 0; k < 4; k++) acc[i][j][k] = 0.0f;

    const int arow  = wm + (lane & 15);
    const int akoff = (lane >> 4) * 8;
    const int brow  = wn + (lane >> 4) * 8 + (lane & 7);
    const int bkoff = ((lane >> 3) & 1) * 8;

    load_stage(0);
    load_stage(1);
    load_stage(2);

    for (int s = 0; s < NSTAGE; s++) {
        const int pend = NSTAGE - 1 - s;
        if (pend >= 2)      asm volatile("cp.async.wait_group 2;" ::: "memory");
        else if (pend == 1) asm volatile("cp.async.wait_group 1;" ::: "memory");
        else                asm volatile("cp.async.wait_group 0;" ::: "memory");
        __syncthreads();
        if (s + 3 < NSTAGE) load_stage(s + 3);

        const int buf = s & (PIPE - 1);
        const uint32_t ab = aoff0 + buf * BUFB;
        const uint32_t bb = boff0 + buf * BUFB;

#pragma unroll
        for (int ksub = 0; ksub < 2; ksub++) {
            uint32_t af[4][4], bf[2][4];
#pragma unroll
            for (int mt = 0; mt < 4; mt++)
                ldsm_x4(af[mt], ab + (uint32_t)((arow + mt * 16) * SA + ksub * 16 + akoff) * 2);
#pragma unroll
            for (int p = 0; p < 2; p++)
                ldsm_x4(bf[p], bb + (uint32_t)((brow + p * 16) * SA + ksub * 16 + bkoff) * 2);
#pragma unroll
            for (int mt = 0; mt < 4; mt++) {
#pragma unroll
                for (int nt = 0; nt < 4; nt++)
                    mma_bf16(acc[mt][nt], af[mt], &bf[nt >> 1][(nt & 1) * 2]);
            }
        }
    }

    // epilogue: direct float2 stores
    const int grp = lane >> 2;
    const int tig = lane & 3;
#pragma unroll
    for (int mt = 0; mt < 4; mt++) {
#pragma unroll
        for (int nt = 0; nt < 4; nt++) {
            const int row = m0 + wm + mt * 16 + grp;
            const int col = n0 + wn + nt * 8 + tig * 2;
            float2 v0 = make_float2(acc[mt][nt][0], acc[mt][nt][1]);
            float2 v1 = make_float2(acc[mt][nt][2], acc[mt][nt][3]);
            *(float2*)&C[(size_t)row * Nn + col]       = v0;
            *(float2*)&C[(size_t)(row + 8) * Nn + col] = v1;
        }
    }
}

// ===========================================================================
// Conversion kernels (unchanged)
// ===========================================================================
__global__ __launch_bounds__(256)
void split_rows(const float* __restrict__ in, __nv_bfloat16* __restrict__ out, int M) {
    int idx = blockIdx.x * 256 + threadIdx.x;
    if (idx >= M * DD) return;
    int m = idx >> 10, k = idx & 1023;
    float x = in[idx];
    __nv_bfloat16 hi = __float2bfloat16(x);
    __nv_bfloat16 lo = __float2bfloat16(x - __bfloat162float(hi));
    __nv_bfloat16* o = out + (size_t)m * KP;
    o[k] = hi; o[DD + k] = lo; o[2 * DD + k] = hi;
}

__global__ __launch_bounds__(256)
void split_transpose(const float* __restrict__ W, __nv_bfloat16* __restrict__ out, int Nw) {
    __shared__ float t[32][33];
    int n0 = blockIdx.x * 32, k0 = blockIdx.y * 32;
    int tx = threadIdx.x, ty = threadIdx.y;
#pragma unroll
    for (int i = ty; i < 32; i += 8)
        t[i][tx] = W[(size_t)(k0 + i) * Nw + n0 + tx];
    __syncthreads();
#pragma unroll
    for (int i = ty; i < 32; i += 8) {
        int n = n0 + i, k = k0 + tx;
        float x = t[tx][i];
        __nv_bfloat16 hi = __float2bfloat16(x);
        __nv_bfloat16 lo = __float2bfloat16(x - __bfloat162float(hi));
        __nv_bfloat16* o = out + (size_t)n * KP;
        o[k] = hi; o[DD + k] = hi; o[2 * DD + k] = lo;
    }
}

// ===========================================================================
// Attention with tf32 mma — unchanged from R4 (passing, 386us)
// ===========================================================================
#define AT_I 128
#define AT_J 64
#define STRD 68
#define SMEM_ATTN ((AT_I + AT_J + AT_J) * STRD * (int)sizeof(float))

__global__ __launch_bounds__(256, 2)
void attn_tc(const float* __restrict__ qkv, float* __restrict__ outp) {
    extern __shared__ float sm[];
    float* Ksm = sm;
    float* Qsm = sm + AT_I * STRD;
    float* Vsm = sm + (AT_I + AT_J) * STRD;

    const int it = blockIdx.x;
    const int bh = blockIdx.y;
    const int b = bh >> 4, h = bh & 15;
    const int i0 = it * AT_I;

    const int tid  = threadIdx.x;
    const int wid  = tid >> 5;
    const int lane = tid & 31;
    const int g = lane >> 2;
    const int t = lane & 3;
    const int wm = wid * 16;

    const size_t RS = 3 * DD;
    const float* Qg = qkv + h * EE;
    const float* Kg = qkv + DD + h * EE;
    const float* Vg = qkv + 2 * DD + h * EE;

#pragma unroll
    for (int q = 0; q < 8; q++) {
        int idx = q * 256 + tid;
        int r = idx >> 4, ec = (idx & 15) << 2;
        float4 v = *(const float4*)(Kg + (size_t)(b * NN + i0 + r) * RS + ec);
        float* d = Ksm + r * STRD + ec;
        d[0] = tf32r(v.x); d[1] = tf32r(v.y); d[2] = tf32r(v.z); d[3] = tf32r(v.w);
    }

    float m0 = -1e30f, m1 = -1e30f, l0 = 0.0f, l1 = 0.0f;
    float O[8][4];
#pragma unroll
    for (int nt = 0; nt < 8; nt++)
#pragma unroll
        for (int k = 0; k < 4; k++) O[nt][k] = 0.0f;

    const int r0g = i0 + wm + g;
    const int r1g = r0g + 8;

    const int jt0 = it * 2;
    const int nJT = NN / AT_J;

    for (int jt = jt0; jt < nJT; jt++) {
        const int j0 = jt * AT_J;
        __syncthreads();

#pragma unroll
        for (int q = 0; q < 4; q++) {
            int idx = q * 256 + tid;
            int r = idx >> 4, ec = (idx & 15) << 2;
            float4 v = *(const float4*)(Qg + (size_t)(b * NN + j0 + r) * RS + ec);
            float* d = Qsm + r * STRD + ec;
            d[0] = tf32r(v.x); d[1] = tf32r(v.y); d[2] = tf32r(v.z); d[3] = tf32r(v.w);
        }
#pragma unroll
        for (int q = 0; q < 4; q++) {
            int ec = (wid * 2 + (q >> 1)) << 2;
            int j  = ((q & 1) << 5) + lane;
            float4 v = *(const float4*)(Vg + (size_t)(b * NN + j0 + j) * RS + ec);
            Vsm[(ec + 0) * STRD + j] = tf32r(v.x);
            Vsm[(ec + 1) * STRD + j] = tf32r(v.y);
            Vsm[(ec + 2) * STRD + j] = tf32r(v.z);
            Vsm[(ec + 3) * STRD + j] = tf32r(v.w);
        }
        __syncthreads();

        float C[8][4];
#pragma unroll
        for (int nt = 0; nt < 8; nt++)
#pragma unroll
            for (int k = 0; k < 4; k++) C[nt][k] = 0.0f;

#pragma unroll
        for (int kt = 0; kt < 8; kt++) {
            float a[4];
            a[0] = Ksm[(wm + g)     * STRD + kt * 8 + t];
            a[1] = Ksm[(wm + g + 8) * STRD + kt * 8 + t];
            a[2] = Ksm[(wm + g)     * STRD + kt * 8 + t + 4];
            a[3] = Ksm[(wm + g + 8) * STRD + kt * 8 + t + 4];
#pragma unroll
            for (int nt = 0; nt < 8; nt++) {
                float b0 = Qsm[(nt * 8 + g) * STRD + kt * 8 + t];
                float b1 = Qsm[(nt * 8 + g) * STRD + kt * 8 + t + 4];
                mma_tf32(C[nt], a, b0, b1);
            }
        }

        const bool needmask = (j0 < i0 + AT_I);
        float rmax0 = -1e30f, rmax1 = -1e30f;
#pragma unroll
        for (int nt = 0; nt < 8; nt++) {
            C[nt][0] *= 0.125f; C[nt][1] *= 0.125f;
            C[nt][2] *= 0.125f; C[nt][3] *= 0.125f;
            if (needmask) {
                int c0 = j0 + nt * 8 + 2 * t;
                int c1 = c0 + 1;
                if (c0 < r0g) C[nt][0] = -1e30f;
                if (c1 < r0g) C[nt][1] = -1e30f;
                if (c0 < r1g) C[nt][2] = -1e30f;
                if (c1 < r1g) C[nt][3] = -1e30f;
            }
            rmax0 = fmaxf(rmax0, fmaxf(C[nt][0], C[nt][1]));
            rmax1 = fmaxf(rmax1, fmaxf(C[nt][2], C[nt][3]));
        }
        rmax0 = fmaxf(rmax0, __shfl_xor_sync(0xffffffffu, rmax0, 1));
        rmax0 = fmaxf(rmax0, __shfl_xor_sync(0xffffffffu, rmax0, 2));
        rmax1 = fmaxf(rmax1, __shfl_xor_sync(0xffffffffu, rmax1, 1));
        rmax1 = fmaxf(rmax1, __shfl_xor_sync(0xffffffffu, rmax1, 2));

        float mn0 = fmaxf(m0, rmax0), mn1 = fmaxf(m1, rmax1);
        float sc0 = __expf(m0 - mn0), sc1 = __expf(m1 - mn1);
        m0 = mn0; m1 = mn1;

        float rs0 = 0.0f, rs1 = 0.0f;
#pragma unroll
        for (int nt = 0; nt < 8; nt++) {
            C[nt][0] = __expf(C[nt][0] - mn0);
            C[nt][1] = __expf(C[nt][1] - mn0);
            C[nt][2] = __expf(C[nt][2] - mn1);
            C[nt][3] = __expf(C[nt][3] - mn1);
            rs0 += C[nt][0] + C[nt][1];
            rs1 += C[nt][2] + C[nt][3];
        }
        rs0 += __shfl_xor_sync(0xffffffffu, rs0, 1);
        rs0 += __shfl_xor_sync(0xffffffffu, rs0, 2);
        rs1 += __shfl_xor_sync(0xffffffffu, rs1, 1);
        rs1 += __shfl_xor_sync(0xffffffffu, rs1, 2);
        l0 = l0 * sc0 + rs0;
        l1 = l1 * sc1 + rs1;
#pragma unroll
        for (int nt = 0; nt < 8; nt++) {
            O[nt][0] *= sc0; O[nt][1] *= sc0;
            O[nt][2] *= sc1; O[nt][3] *= sc1;
        }

        const uint32_t srcA = (lane & 28) | (t >> 1);
        const uint32_t srcB = srcA + 2;
#pragma unroll
        for (int kt = 0; kt < 8; kt++) {
            float p0a = __shfl_sync(0xffffffffu, C[kt][0], srcA);
            float p1a = __shfl_sync(0xffffffffu, C[kt][1], srcA);
            float p2a = __shfl_sync(0xffffffffu, C[kt][2], srcA);
            float p3a = __shfl_sync(0xffffffffu, C[kt][3], srcA);
            float p0b = __shfl_sync(0xffffffffu, C[kt][0], srcB);
            float p1b = __shfl_sync(0xffffffffu, C[kt][1], srcB);
            float p2b = __shfl_sync(0xffffffffu, C[kt][2], srcB);
            float p3b = __shfl_sync(0xffffffffu, C[kt][3], srcB);
            float a[4];
            a[0] = tf32r((t & 1) ? p1a : p0a);
            a[1] = tf32r((t & 1) ? p3a : p2a);
            a[2] = tf32r((t & 1) ? p1b : p0b);
            a[3] = tf32r((t & 1) ? p3b : p2b);
#pragma unroll
            for (int nt = 0; nt < 8; nt++) {
                float b0 = Vsm[(nt * 8 + g) * STRD + kt * 8 + t];
                float b1 = Vsm[(nt * 8 + g) * STRD + kt * 8 + t + 4];
                mma_tf32(O[nt], a, b0, b1);
            }
        }
    }

    float inv0 = 1.0f / l0, inv1 = 1.0f / l1;
    float* out0 = outp + (size_t)(b * NN + r0g) * DD + h * EE;
    float* out1 = outp + (size_t)(b * NN + r1g) * DD + h * EE;
#pragma unroll
    for (int nt = 0; nt < 8; nt++) {
        int col = nt * 8 + 2 * t;
        *(float2*)(out0 + col) = make_float2(O[nt][0] * inv0, O[nt][1] * inv0);
        *(float2*)(out1 + col) = make_float2(O[nt][2] * inv1, O[nt][3] * inv1);
    }
}

// ===========================================================================
extern "C" void kernel_launch(void* const* d_in, const int* in_sizes, int n_in,
                              void* d_out, int out_size) {
    const float* x    = (const float*)d_in[0];
    const float* Wqkv = (const float*)d_in[1];
    const float* Wo   = (const float*)d_in[2];
    float* out = (float*)d_out;

    float* qkv = nullptr;  float* attn = nullptr;
    __nv_bfloat16* Abuf = nullptr;  __nv_bfloat16* Bbuf = nullptr;
    cudaGetSymbolAddress((void**)&qkv,  g_qkv);
    cudaGetSymbolAddress((void**)&attn, g_attn);
    cudaGetSymbolAddress((void**)&Abuf, g_A);
    cudaGetSymbolAddress((void**)&Bbuf, g_B);

    cudaFuncSetAttribute(gemm_hmma, cudaFuncAttributeMaxDynamicSharedMemorySize, SMEM_GEMM);
    cudaFuncSetAttribute(attn_tc, cudaFuncAttributeMaxDynamicSharedMemorySize, SMEM_ATTN);

    // 1) x -> A' split
    split_rows<<<(MTOT * DD + 255) / 256, 256>>>(x, Abuf, MTOT);
    // 2) W_qkv -> B' split-transpose
    split_transpose<<<dim3(3 * DD / 32, DD / 32), dim3(32, 8)>>>(Wqkv, Bbuf, 3 * DD);
    // 3) QKV GEMM
    gemm_hmma<<<dim3(3 * DD / 128, MTOT / 128), 256, SMEM_GEMM>>>(Abuf, Bbuf, qkv, MTOT, 3 * DD);
    // 4) attention (tf32 tensor cores)
    attn_tc<<<dim3(NN / AT_I, BB * HH), 256, SMEM_ATTN>>>(qkv, attn);
    // 5) attn out -> A' ; W_o -> B'
    split_rows<<<(MTOT * DD + 255) / 256, 256>>>(attn, Abuf, MTOT);
    split_transpose<<<dim3(DD / 32, DD / 32), dim3(32, 8)>>>(Wo, Bbuf, DD);
    // 6) O-proj GEMM
    gemm_hmma<<<dim3(DD / 128, MTOT / 128), 256, SMEM_GEMM>>>(Abuf, Bbuf, out, MTOT, DD);
}